// round 1
// baseline (speedup 1.0000x reference)
#include <cuda_runtime.h>
#include <cuda_bf16.h>
#include <math.h>

#define NE 32768
#define NSTEP 65535   // 2*NE - 1

// ---------------- device scratch (static, no allocation) ----------------
__device__ float g_encp[NE * 200];      // projected encodings (h|c), 26.2MB
__device__ float g_P[NE * 500];         // precomputed W_e @ h_e + b_tree, 65.5MB
__device__ float g_X[NE * 200];         // merge chain states (h|c), 26.2MB
__device__ float g_WtProj[768 * 200];   // W_proj transposed [k][j]
__device__ float g_WtE[100 * 500];      // W_tree[:,100:200] transposed [c][r]
__device__ float g_WL[600 * 24];        // concat loss weights, [col][out]
__device__ float g_bL[24];
__device__ float g_losses[NSTEP];

__device__ __forceinline__ float sigf(float x)  { return 1.f / (1.f + __expf(-x)); }
__device__ __forceinline__ float tanh_f(float x){ return 1.f - 2.f / (__expf(2.f * x) + 1.f); }

// ---------------- prep: transposes / packing ----------------
__global__ void prep_kernel(const float* __restrict__ Wproj,
                            const float* __restrict__ Wtree,
                            const float* __restrict__ Wact,
                            const float* __restrict__ Wlab,
                            const float* __restrict__ Wdir,
                            const float* __restrict__ bact,
                            const float* __restrict__ blab,
                            const float* __restrict__ bdir) {
    int i = blockIdx.x * blockDim.x + threadIdx.x;
    int stride = gridDim.x * blockDim.x;
    for (int e = i; e < 768 * 200; e += stride) {
        int k = e / 200, j = e % 200;
        g_WtProj[e] = Wproj[j * 768 + k];
    }
    for (int e = i; e < 100 * 500; e += stride) {
        int c = e / 500, r = e % 500;
        g_WtE[e] = Wtree[r * 200 + 100 + c];
    }
    for (int e = i; e < 600 * 24; e += stride) {
        int c = e / 24, q = e % 24;
        float v;
        if (q < 2)       v = Wact[q * 600 + c];
        else if (q < 21) v = Wlab[(q - 2) * 600 + c];
        else             v = Wdir[(q - 21) * 600 + c];
        g_WL[e] = v;
    }
    if (i < 24) {
        g_bL[i] = (i < 2) ? bact[i] : (i < 21) ? blab[i - 2] : bdir[i - 21];
    }
}

// ---------------- generic fp32 GEMM: C[M,N] = A[M,lda] * B[K,N] + bias ----------------
// block = 128 threads, tile 64x64, BK=16, thread tile 4x8. M multiple of 64.
__global__ void gemm_kernel(const float* __restrict__ A, int lda,
                            const float* __restrict__ B,
                            const float* __restrict__ bias,
                            float* __restrict__ C, int ldc,
                            int N, int K) {
    __shared__ float As[16][68];   // transposed A tile, padded
    __shared__ float Bs[16][64];
    int m0 = blockIdx.y * 64;
    int n0 = blockIdx.x * 64;
    int tid = threadIdx.x;
    int r0 = (tid >> 3) * 4;
    int c0 = (tid & 7) * 8;
    float acc[4][8];
    #pragma unroll
    for (int i = 0; i < 4; i++)
        #pragma unroll
        for (int j = 0; j < 8; j++) acc[i][j] = 0.f;

    for (int k0 = 0; k0 < K; k0 += 16) {
        #pragma unroll
        for (int i = 0; i < 8; i++) {
            int e = tid + 128 * i;
            int m = e >> 4, k = e & 15;
            As[k][m] = (k0 + k < K) ? A[(m0 + m) * lda + k0 + k] : 0.f;
        }
        #pragma unroll
        for (int i = 0; i < 8; i++) {
            int e = tid + 128 * i;
            int k = e >> 6, n = e & 63;
            float v = 0.f;
            if (k0 + k < K && n0 + n < N) v = B[(k0 + k) * N + n0 + n];
            Bs[k][n] = v;
        }
        __syncthreads();
        #pragma unroll
        for (int kk = 0; kk < 16; kk++) {
            float a[4];
            #pragma unroll
            for (int i = 0; i < 4; i++) a[i] = As[kk][r0 + i];
            float4 b0 = *(const float4*)&Bs[kk][c0];
            float4 b1 = *(const float4*)&Bs[kk][c0 + 4];
            float b[8] = {b0.x, b0.y, b0.z, b0.w, b1.x, b1.y, b1.z, b1.w};
            #pragma unroll
            for (int i = 0; i < 4; i++)
                #pragma unroll
                for (int j = 0; j < 8; j++) acc[i][j] += a[i] * b[j];
        }
        __syncthreads();
    }
    #pragma unroll
    for (int i = 0; i < 4; i++) {
        int m = m0 + r0 + i;
        #pragma unroll
        for (int j = 0; j < 8; j++) {
            int n = n0 + c0 + j;
            if (n < N) C[m * ldc + n] = acc[i][j] + bias[n];
        }
    }
}

// ---------------- sequential TreeLSTM chain (single CTA) ----------------
// g = W_h @ h_prev + P[m]; gates -> (h,c); store X[m].
// Threads 0..999: matvec, 2 threads/row, 50 weights each in registers.
// Threads 1000..1023: prefetch P[m] (500) + c_e[m] (100) into SMEM.
__global__ void __launch_bounds__(1024, 1) chain_kernel(const float* __restrict__ Wtree) {
    __shared__ float hs[100];
    __shared__ float gs[500];
    __shared__ float psm[600];   // [0..499] = P row, [500..599] = c_e row
    int tid = threadIdx.x;
    int r = tid >> 1, half = tid & 1;

    float w[50];
    if (tid < 1000) {
        #pragma unroll
        for (int c = 0; c < 50; c++) w[c] = Wtree[r * 200 + half * 50 + c];
    } else {
        #pragma unroll
        for (int c = 0; c < 50; c++) w[c] = 0.f;
    }

    float cprev = 0.f;
    if (tid < 100) {
        float h0 = g_encp[tid];
        cprev = g_encp[100 + tid];
        hs[tid] = h0;
        g_X[tid] = h0;
        g_X[100 + tid] = cprev;
    }
    __syncthreads();

    for (int m = 1; m <= NE - 2; m++) {
        if (tid < 1000) {
            const float* hb = hs + half * 50;
            float a0 = 0.f, a1 = 0.f;
            #pragma unroll
            for (int c = 0; c < 50; c += 2) {
                a0 += w[c] * hb[c];
                a1 += w[c + 1] * hb[c + 1];
            }
            float acc = a0 + a1;
            unsigned mask = (tid < 992) ? 0xffffffffu : 0x000000ffu;
            acc += __shfl_xor_sync(mask, acc, 1);
            if (half == 0) gs[r] = acc;
        } else {
            int p = tid - 1000;
            const float* Pm = g_P + m * 500;
            const float* cem = g_encp + m * 200 + 100;
            #pragma unroll
            for (int k = 0; k < 25; k++) {
                int idx = p + 24 * k;
                psm[idx] = (idx < 500) ? Pm[idx] : cem[idx - 500];
            }
        }
        __syncthreads();
        if (tid < 100) {
            float gi  = gs[tid]       + psm[tid];
            float gf1 = gs[100 + tid] + psm[100 + tid];
            float gf2 = gs[200 + tid] + psm[200 + tid];
            float go  = gs[300 + tid] + psm[300 + tid];
            float gu  = gs[400 + tid] + psm[400 + tid];
            float ce2 = psm[500 + tid];
            float cc = sigf(gi) * tanh_f(gu) + sigf(gf1) * cprev + sigf(gf2) * ce2;
            float hh = sigf(go) * tanh_f(cc);
            cprev = cc;
            hs[tid] = hh;
            float* Xm = g_X + m * 200;
            Xm[tid] = hh;
            Xm[100 + tid] = cc;
        }
        __syncthreads();
    }
}

// ---------------- per-step losses (parallel) ----------------
__device__ __forceinline__ float ce_all(const float* l, int a, int lb, int dr) {
    float m0 = fmaxf(l[0], l[1]);
    float loss = m0 + __logf(__expf(l[0] - m0) + __expf(l[1] - m0)) - l[a];
    float m1 = l[2];
    #pragma unroll
    for (int q = 3; q < 21; q++) m1 = fmaxf(m1, l[q]);
    float s1 = 0.f;
    #pragma unroll
    for (int q = 2; q < 21; q++) s1 += __expf(l[q] - m1);
    loss += m1 + __logf(s1) - l[2 + lb];
    float m2 = fmaxf(fmaxf(l[21], l[22]), l[23]);
    float s2 = __expf(l[21] - m2) + __expf(l[22] - m2) + __expf(l[23] - m2);
    loss += m2 + __logf(s2) - l[21 + dr];
    return loss;
}

// block = 256 threads, 16 steps/block; each warp computes 2 steps.
__global__ void loss_kernel(const float* __restrict__ missing,
                            const int* __restrict__ ga,
                            const int* __restrict__ gl,
                            const int* __restrict__ gd) {
    __shared__ float fs[16][600];
    int t0 = blockIdx.x * 16;
    int tid = threadIdx.x;

    // gather feats = [s1, s0, b]
    for (int e = tid; e < 16 * 600; e += 256) {
        int s = e / 600, c = e % 600;
        int t = t0 + s;
        float v = 0.f;
        if (t < NSTEP) {
            const float* src;
            int base;
            if (c < 200) {          // s1
                base = 0;
                if ((t & 1) == 0 && t >= 2) src = g_X + (t / 2 - 1) * 200;
                else                         src = missing;
            } else if (c < 400) {   // s0
                base = 200;
                if (t & 1)       src = g_X + (t / 2) * 200;
                else             src = (t == 0) ? missing : (g_encp + (t / 2) * 200);
            } else {                // b
                base = 400;
                if (t == 0) src = g_encp;
                else {
                    int idx = t / 2 + 1;
                    src = (idx < NE) ? (g_encp + idx * 200) : missing;
                }
            }
            v = src[c - base];
        }
        fs[s][c] = v;
    }
    __syncthreads();

    int warp = tid >> 5, lane = tid & 31;
    const float* f0 = fs[warp * 2];
    const float* f1 = fs[warp * 2 + 1];
    float acc0[24], acc1[24];
    #pragma unroll
    for (int q = 0; q < 24; q++) { acc0[q] = 0.f; acc1[q] = 0.f; }

    for (int c = lane; c < 600; c += 32) {
        float fa = f0[c], fb = f1[c];
        const float4* wp = (const float4*)(g_WL + c * 24);
        #pragma unroll
        for (int v4 = 0; v4 < 6; v4++) {
            float4 wv = wp[v4];
            acc0[v4 * 4 + 0] += wv.x * fa;  acc1[v4 * 4 + 0] += wv.x * fb;
            acc0[v4 * 4 + 1] += wv.y * fa;  acc1[v4 * 4 + 1] += wv.y * fb;
            acc0[v4 * 4 + 2] += wv.z * fa;  acc1[v4 * 4 + 2] += wv.z * fb;
            acc0[v4 * 4 + 3] += wv.w * fa;  acc1[v4 * 4 + 3] += wv.w * fb;
        }
    }
    #pragma unroll
    for (int off = 16; off; off >>= 1) {
        #pragma unroll
        for (int q = 0; q < 24; q++) {
            acc0[q] += __shfl_xor_sync(0xffffffffu, acc0[q], off);
            acc1[q] += __shfl_xor_sync(0xffffffffu, acc1[q], off);
        }
    }
    if (lane == 0) {
        int ta = t0 + warp * 2;
        if (ta < NSTEP) {
            float l[24];
            #pragma unroll
            for (int q = 0; q < 24; q++) l[q] = acc0[q] + g_bL[q];
            g_losses[ta] = ce_all(l, ga[ta], gl[ta], gd[ta]);
        }
        int tb = ta + 1;
        if (tb < NSTEP) {
            float l[24];
            #pragma unroll
            for (int q = 0; q < 24; q++) l[q] = acc1[q] + g_bL[q];
            g_losses[tb] = ce_all(l, ga[tb], gl[tb], gd[tb]);
        }
    }
}

// ---------------- deterministic final reduction ----------------
__global__ void reduce_kernel(float* __restrict__ out) {
    __shared__ float ss[1024];
    float s = 0.f;
    for (int i = threadIdx.x; i < NSTEP; i += 1024) s += g_losses[i];
    ss[threadIdx.x] = s;
    __syncthreads();
    for (int o = 512; o; o >>= 1) {
        if (threadIdx.x < o) ss[threadIdx.x] += ss[threadIdx.x + o];
        __syncthreads();
    }
    if (threadIdx.x == 0) out[0] = ss[0];
}

// ---------------- launch ----------------
extern "C" void kernel_launch(void* const* d_in, const int* in_sizes, int n_in,
                              void* d_out, int out_size) {
    const float* enc_cls = (const float*)d_in[0];
    const float* W_proj  = (const float*)d_in[1];
    const float* b_proj  = (const float*)d_in[2];
    const float* missing = (const float*)d_in[3];
    const float* W_act   = (const float*)d_in[4];
    const float* b_act   = (const float*)d_in[5];
    const float* W_lab   = (const float*)d_in[6];
    const float* b_lab   = (const float*)d_in[7];
    const float* W_dir   = (const float*)d_in[8];
    const float* b_dir   = (const float*)d_in[9];
    const float* W_tree  = (const float*)d_in[10];
    const float* b_tree  = (const float*)d_in[11];
    const int*   ga      = (const int*)d_in[12];
    const int*   gl      = (const int*)d_in[13];
    const int*   gd      = (const int*)d_in[14];

    void *p_encp, *p_P, *p_WtProj, *p_WtE;
    cudaGetSymbolAddress(&p_encp, g_encp);
    cudaGetSymbolAddress(&p_P, g_P);
    cudaGetSymbolAddress(&p_WtProj, g_WtProj);
    cudaGetSymbolAddress(&p_WtE, g_WtE);

    prep_kernel<<<128, 256>>>(W_proj, W_tree, W_act, W_lab, W_dir, b_act, b_lab, b_dir);

    // enc_proj = enc_cls @ W_proj^T + b_proj   (M=32768, N=200, K=768)
    gemm_kernel<<<dim3(4, 512), 128>>>(enc_cls, 768, (const float*)p_WtProj,
                                       b_proj, (float*)p_encp, 200, 200, 768);

    // P = enc_proj[:, :100] @ W_e^T + b_tree   (M=32768, N=500, K=100)
    gemm_kernel<<<dim3(8, 512), 128>>>((const float*)p_encp, 200, (const float*)p_WtE,
                                       b_tree, (float*)p_P, 500, 500, 100);

    chain_kernel<<<1, 1024>>>(W_tree);

    loss_kernel<<<4096, 256>>>(missing, ga, gl, gd);

    reduce_kernel<<<1, 1024>>>((float*)d_out);
}

// round 2
// speedup vs baseline: 1.8876x; 1.8876x over previous
#include <cuda_runtime.h>
#include <cuda_bf16.h>
#include <math.h>

#define NE 32768
#define NSTEP 65535   // 2*NE - 1

// ---------------- device scratch (static, no allocation) ----------------
__device__ __align__(16) float g_encp[NE * 200];      // projected encodings (h|c)
__device__ __align__(16) float g_PC[NE * 640];        // [0..500)=P row, [512..612)=c_e, padded
__device__ __align__(16) float g_X[NE * 200];         // merge chain states (h|c)
__device__ __align__(16) float g_WtProj[768 * 200];   // W_proj transposed
__device__ __align__(16) float g_WtE[100 * 500];      // W_tree[:,100:200] transposed
__device__ __align__(16) float g_WL[600 * 24];        // concat loss weights, [col][out]
__device__ float g_bL[24];
__device__ float g_losses[NSTEP];

__device__ __forceinline__ float sigf(float x)  { return 1.f / (1.f + __expf(-x)); }
__device__ __forceinline__ float tanh_f(float x){ return 1.f - 2.f / (__expf(2.f * x) + 1.f); }

#define FMA2(acc, a, b) asm("fma.rn.f32x2 %0, %1, %2, %0;" : "+l"(acc) : "l"(a), "l"(b))

// ---------------- prep: transposes / packing ----------------
__global__ void prep_kernel(const float* __restrict__ Wproj,
                            const float* __restrict__ Wtree,
                            const float* __restrict__ Wact,
                            const float* __restrict__ Wlab,
                            const float* __restrict__ Wdir,
                            const float* __restrict__ bact,
                            const float* __restrict__ blab,
                            const float* __restrict__ bdir) {
    int i = blockIdx.x * blockDim.x + threadIdx.x;
    int stride = gridDim.x * blockDim.x;
    for (int e = i; e < 768 * 200; e += stride) {
        int k = e / 200, j = e % 200;
        g_WtProj[e] = Wproj[j * 768 + k];
    }
    for (int e = i; e < 100 * 500; e += stride) {
        int c = e / 500, r = e % 500;
        g_WtE[e] = Wtree[r * 200 + 100 + c];
    }
    for (int e = i; e < 600 * 24; e += stride) {
        int c = e / 24, q = e % 24;
        float v;
        if (q < 2)       v = Wact[q * 600 + c];
        else if (q < 21) v = Wlab[(q - 2) * 600 + c];
        else             v = Wdir[(q - 21) * 600 + c];
        g_WL[e] = v;
    }
    if (i < 24) {
        g_bL[i] = (i < 2) ? bact[i] : (i < 21) ? blab[i - 2] : bdir[i - 21];
    }
}

// ---------------- generic fp32 GEMM: C[M,N] = A[M,lda] * B[K,N] + bias ----------------
__global__ void gemm_kernel(const float* __restrict__ A, int lda,
                            const float* __restrict__ B,
                            const float* __restrict__ bias,
                            float* __restrict__ C, int ldc,
                            int N, int K) {
    __shared__ float As[16][68];
    __shared__ float Bs[16][64];
    int m0 = blockIdx.y * 64;
    int n0 = blockIdx.x * 64;
    int tid = threadIdx.x;
    int r0 = (tid >> 3) * 4;
    int c0 = (tid & 7) * 8;
    float acc[4][8];
    #pragma unroll
    for (int i = 0; i < 4; i++)
        #pragma unroll
        for (int j = 0; j < 8; j++) acc[i][j] = 0.f;

    for (int k0 = 0; k0 < K; k0 += 16) {
        #pragma unroll
        for (int i = 0; i < 8; i++) {
            int e = tid + 128 * i;
            int m = e >> 4, k = e & 15;
            As[k][m] = (k0 + k < K) ? A[(m0 + m) * lda + k0 + k] : 0.f;
        }
        #pragma unroll
        for (int i = 0; i < 8; i++) {
            int e = tid + 128 * i;
            int k = e >> 6, n = e & 63;
            float v = 0.f;
            if (k0 + k < K && n0 + n < N) v = B[(k0 + k) * N + n0 + n];
            Bs[k][n] = v;
        }
        __syncthreads();
        #pragma unroll
        for (int kk = 0; kk < 16; kk++) {
            float a[4];
            #pragma unroll
            for (int i = 0; i < 4; i++) a[i] = As[kk][r0 + i];
            float4 b0 = *(const float4*)&Bs[kk][c0];
            float4 b1 = *(const float4*)&Bs[kk][c0 + 4];
            float b[8] = {b0.x, b0.y, b0.z, b0.w, b1.x, b1.y, b1.z, b1.w};
            #pragma unroll
            for (int i = 0; i < 4; i++)
                #pragma unroll
                for (int j = 0; j < 8; j++) acc[i][j] += a[i] * b[j];
        }
        __syncthreads();
    }
    #pragma unroll
    for (int i = 0; i < 4; i++) {
        int m = m0 + r0 + i;
        #pragma unroll
        for (int j = 0; j < 8; j++) {
            int n = n0 + c0 + j;
            if (n < N) C[m * ldc + n] = acc[i][j] + bias[n];
        }
    }
}

// ---------------- copy c_e into the packed PC rows ----------------
__global__ void copyc_kernel() {
    int i = blockIdx.x * blockDim.x + threadIdx.x;
    int stride = gridDim.x * blockDim.x;
    // 25 float4 per row
    for (int e = i; e < NE * 25; e += stride) {
        int m = e / 25, q = e % 25;
        const float4* src = (const float4*)(g_encp + (size_t)m * 200 + 100);
        float4* dst = (float4*)(g_PC + (size_t)m * 640 + 512);
        dst[q] = src[q];
    }
}

// ---------------- sequential TreeLSTM chain (single CTA, pipelined) ----------------
// Threads 0..999: matvec g = W_h @ h_prev (2 threads/row, 25 packed f32x2 each).
// Threads 1000..1023: cp.async prefetch of PC row m+2 into a 3-slot SMEM ring.
// Threads 0..99 then apply gates.
__global__ void __launch_bounds__(1024, 1) chain_kernel(const float* __restrict__ Wtree) {
    __shared__ __align__(16) float hs[104];
    __shared__ __align__(16) float gs[512];
    __shared__ __align__(16) float psm[3][640];
    int tid = threadIdx.x;
    int r = tid >> 1, half = tid & 1;

    // pack 25 x f32x2 weights into registers (cols [half*50, half*50+50) of row r)
    unsigned long long w2[25];
    if (tid < 1000) {
        const float* wb = Wtree + r * 200 + half * 50;
        #pragma unroll
        for (int c = 0; c < 25; c++) {
            float lo = wb[2 * c], hi = wb[2 * c + 1];
            w2[c] = ((unsigned long long)__float_as_uint(hi) << 32) | __float_as_uint(lo);
        }
    } else {
        #pragma unroll
        for (int c = 0; c < 25; c++) w2[c] = 0ull;
    }

    float cprev = 0.f;
    if (tid < 100) {
        float h0 = g_encp[tid];
        cprev = g_encp[100 + tid];
        hs[tid] = h0;
        g_X[tid] = h0;
        g_X[100 + tid] = cprev;
    }

    // prologue: prefetch PC rows 1 and 2
    if (tid >= 1000) {
        int p = tid - 1000;
        #pragma unroll
        for (int s = 1; s <= 2; s++) {
            const float4* src = (const float4*)(g_PC + (size_t)s * 640);
            unsigned sdst = (unsigned)__cvta_generic_to_shared(&psm[s % 3][0]);
            for (int k = p; k < 160; k += 24) {
                asm volatile("cp.async.cg.shared.global [%0], [%1], 16;\n"
                             :: "r"(sdst + k * 16), "l"(src + k) : "memory");
            }
            asm volatile("cp.async.commit_group;\n" ::: "memory");
        }
    }
    __syncthreads();

    for (int m = 1; m <= NE - 2; m++) {
        if (tid >= 1000) {
            int p = tid - 1000;
            int mp = m + 2;
            if (mp < NE) {
                const float4* src = (const float4*)(g_PC + (size_t)mp * 640);
                unsigned sdst = (unsigned)__cvta_generic_to_shared(&psm[mp % 3][0]);
                for (int k = p; k < 160; k += 24) {
                    asm volatile("cp.async.cg.shared.global [%0], [%1], 16;\n"
                                 :: "r"(sdst + k * 16), "l"(src + k) : "memory");
                }
            }
            asm volatile("cp.async.commit_group;\n" ::: "memory");
            asm volatile("cp.async.wait_group 2;\n" ::: "memory");
        } else {
            const unsigned long long* hb = (const unsigned long long*)(hs + half * 50);
            unsigned long long a0 = 0ull, a1 = 0ull;
            #pragma unroll
            for (int c = 0; c < 25; c += 2) {
                unsigned long long hv = hb[c];
                FMA2(a0, w2[c], hv);
                if (c + 1 < 25) {
                    unsigned long long hv1 = hb[c + 1];
                    FMA2(a1, w2[c + 1], hv1);
                }
            }
            unsigned lo0 = (unsigned)a0, hi0 = (unsigned)(a0 >> 32);
            unsigned lo1 = (unsigned)a1, hi1 = (unsigned)(a1 >> 32);
            float acc = (__uint_as_float(lo0) + __uint_as_float(hi0)) +
                        (__uint_as_float(lo1) + __uint_as_float(hi1));
            unsigned mask = (tid < 992) ? 0xffffffffu : 0x000000ffu;
            acc += __shfl_xor_sync(mask, acc, 1);
            if (half == 0) gs[r] = acc;
        }
        __syncthreads();
        if (tid < 100) {
            const float* P = psm[m % 3];
            float gi  = gs[tid]       + P[tid];
            float gf1 = gs[100 + tid] + P[100 + tid];
            float gf2 = gs[200 + tid] + P[200 + tid];
            float go  = gs[300 + tid] + P[300 + tid];
            float gu  = gs[400 + tid] + P[400 + tid];
            float ce2 = P[512 + tid];
            float cc = sigf(gi) * tanh_f(gu) + sigf(gf1) * cprev + sigf(gf2) * ce2;
            float hh = sigf(go) * tanh_f(cc);
            cprev = cc;
            hs[tid] = hh;
            float* Xm = g_X + (size_t)m * 200;
            Xm[tid] = hh;
            Xm[100 + tid] = cc;
        }
        __syncthreads();
    }
}

// ---------------- per-step losses (parallel) ----------------
__device__ __forceinline__ float ce_all(const float* l, int a, int lb, int dr) {
    float m0 = fmaxf(l[0], l[1]);
    float loss = m0 + __logf(__expf(l[0] - m0) + __expf(l[1] - m0)) - l[a];
    float m1 = l[2];
    #pragma unroll
    for (int q = 3; q < 21; q++) m1 = fmaxf(m1, l[q]);
    float s1 = 0.f;
    #pragma unroll
    for (int q = 2; q < 21; q++) s1 += __expf(l[q] - m1);
    loss += m1 + __logf(s1) - l[2 + lb];
    float m2 = fmaxf(fmaxf(l[21], l[22]), l[23]);
    float s2 = __expf(l[21] - m2) + __expf(l[22] - m2) + __expf(l[23] - m2);
    loss += m2 + __logf(s2) - l[21 + dr];
    return loss;
}

__global__ void loss_kernel(const float* __restrict__ missing,
                            const int* __restrict__ ga,
                            const int* __restrict__ gl,
                            const int* __restrict__ gd) {
    __shared__ float fs[16][600];
    int t0 = blockIdx.x * 16;
    int tid = threadIdx.x;

    for (int e = tid; e < 16 * 600; e += 256) {
        int s = e / 600, c = e % 600;
        int t = t0 + s;
        float v = 0.f;
        if (t < NSTEP) {
            const float* src;
            int base;
            if (c < 200) {          // s1
                base = 0;
                if ((t & 1) == 0 && t >= 2) src = g_X + (size_t)(t / 2 - 1) * 200;
                else                         src = missing;
            } else if (c < 400) {   // s0
                base = 200;
                if (t & 1)       src = g_X + (size_t)(t / 2) * 200;
                else             src = (t == 0) ? missing : (g_encp + (size_t)(t / 2) * 200);
            } else {                // b
                base = 400;
                if (t == 0) src = g_encp;
                else {
                    int idx = t / 2 + 1;
                    src = (idx < NE) ? (g_encp + (size_t)idx * 200) : missing;
                }
            }
            v = src[c - base];
        }
        fs[s][c] = v;
    }
    __syncthreads();

    int warp = tid >> 5, lane = tid & 31;
    const float* f0 = fs[warp * 2];
    const float* f1 = fs[warp * 2 + 1];
    float acc0[24], acc1[24];
    #pragma unroll
    for (int q = 0; q < 24; q++) { acc0[q] = 0.f; acc1[q] = 0.f; }

    for (int c = lane; c < 600; c += 32) {
        float fa = f0[c], fb = f1[c];
        const float4* wp = (const float4*)(g_WL + c * 24);
        #pragma unroll
        for (int v4 = 0; v4 < 6; v4++) {
            float4 wv = wp[v4];
            acc0[v4 * 4 + 0] += wv.x * fa;  acc1[v4 * 4 + 0] += wv.x * fb;
            acc0[v4 * 4 + 1] += wv.y * fa;  acc1[v4 * 4 + 1] += wv.y * fb;
            acc0[v4 * 4 + 2] += wv.z * fa;  acc1[v4 * 4 + 2] += wv.z * fb;
            acc0[v4 * 4 + 3] += wv.w * fa;  acc1[v4 * 4 + 3] += wv.w * fb;
        }
    }
    #pragma unroll
    for (int off = 16; off; off >>= 1) {
        #pragma unroll
        for (int q = 0; q < 24; q++) {
            acc0[q] += __shfl_xor_sync(0xffffffffu, acc0[q], off);
            acc1[q] += __shfl_xor_sync(0xffffffffu, acc1[q], off);
        }
    }
    if (lane == 0) {
        int ta = t0 + warp * 2;
        if (ta < NSTEP) {
            float l[24];
            #pragma unroll
            for (int q = 0; q < 24; q++) l[q] = acc0[q] + g_bL[q];
            g_losses[ta] = ce_all(l, ga[ta], gl[ta], gd[ta]);
        }
        int tb = ta + 1;
        if (tb < NSTEP) {
            float l[24];
            #pragma unroll
            for (int q = 0; q < 24; q++) l[q] = acc1[q] + g_bL[q];
            g_losses[tb] = ce_all(l, ga[tb], gl[tb], gd[tb]);
        }
    }
}

// ---------------- deterministic final reduction ----------------
__global__ void reduce_kernel(float* __restrict__ out) {
    __shared__ float ss[1024];
    float s = 0.f;
    for (int i = threadIdx.x; i < NSTEP; i += 1024) s += g_losses[i];
    ss[threadIdx.x] = s;
    __syncthreads();
    for (int o = 512; o; o >>= 1) {
        if (threadIdx.x < o) ss[threadIdx.x] += ss[threadIdx.x + o];
        __syncthreads();
    }
    if (threadIdx.x == 0) out[0] = ss[0];
}

// ---------------- launch ----------------
extern "C" void kernel_launch(void* const* d_in, const int* in_sizes, int n_in,
                              void* d_out, int out_size) {
    const float* enc_cls = (const float*)d_in[0];
    const float* W_proj  = (const float*)d_in[1];
    const float* b_proj  = (const float*)d_in[2];
    const float* missing = (const float*)d_in[3];
    const float* W_act   = (const float*)d_in[4];
    const float* b_act   = (const float*)d_in[5];
    const float* W_lab   = (const float*)d_in[6];
    const float* b_lab   = (const float*)d_in[7];
    const float* W_dir   = (const float*)d_in[8];
    const float* b_dir   = (const float*)d_in[9];
    const float* W_tree  = (const float*)d_in[10];
    const float* b_tree  = (const float*)d_in[11];
    const int*   ga      = (const int*)d_in[12];
    const int*   gl      = (const int*)d_in[13];
    const int*   gd      = (const int*)d_in[14];

    void *p_encp, *p_PC, *p_WtProj, *p_WtE;
    cudaGetSymbolAddress(&p_encp, g_encp);
    cudaGetSymbolAddress(&p_PC, g_PC);
    cudaGetSymbolAddress(&p_WtProj, g_WtProj);
    cudaGetSymbolAddress(&p_WtE, g_WtE);

    prep_kernel<<<128, 256>>>(W_proj, W_tree, W_act, W_lab, W_dir, b_act, b_lab, b_dir);

    // enc_proj = enc_cls @ W_proj^T + b_proj   (M=32768, N=200, K=768)
    gemm_kernel<<<dim3(4, 512), 128>>>(enc_cls, 768, (const float*)p_WtProj,
                                       b_proj, (float*)p_encp, 200, 200, 768);

    // P = enc_proj[:, :100] @ W_e^T + b_tree   (M=32768, N=500, K=100) -> packed rows
    gemm_kernel<<<dim3(8, 512), 128>>>((const float*)p_encp, 200, (const float*)p_WtE,
                                       b_tree, (float*)p_PC, 640, 500, 100);

    copyc_kernel<<<256, 256>>>();

    chain_kernel<<<1, 1024>>>(W_tree);

    loss_kernel<<<4096, 256>>>(missing, ga, gl, gd);

    reduce_kernel<<<1, 1024>>>((float*)d_out);
}